// round 16
// baseline (speedup 1.0000x reference)
#include <cuda_runtime.h>
#include <cuda_fp16.h>

#define C 32
#define NMAX 100000
#define EMAX 1600000
#define FULLMASK 0xffffffffu
#define WPB 8          // warps per block (256 threads)

typedef unsigned int uint32;

// ---------------- device scratch ----------------
__device__ uint2  g_Hd16[NMAX * 8];    // fp16 Hd rows: [node][quad] = 4 halves
__device__ uint2  g_Hs16[NMAX * 8];    // fp16 Hs rows
__device__ float  g_Vs [NMAX * C];
__device__ float2 g_da2[NMAX * C];     // per node/channel: {den, acc}
__device__ int2   g_edge[EMAX];        // packed (src*C, dst*C) element offsets
__device__ __half g_hh[(long long)EMAX * C]; // pre-BN h fp16, row layout [e][c]
__device__ float  g_c0 [C];            // Wa1 @ bp + ba1 (written by k_node blk0)
__device__ double g_sum  [C];
__device__ double g_sumsq[C];

// ---------------- mma helpers ----------------
__device__ __forceinline__ void ldm_x4(uint32& r0, uint32& r1, uint32& r2, uint32& r3,
                                       uint32 addr) {
    asm volatile("ldmatrix.sync.aligned.m8n8.x4.shared.b16 {%0,%1,%2,%3}, [%4];"
                 : "=r"(r0), "=r"(r1), "=r"(r2), "=r"(r3) : "r"(addr));
}
__device__ __forceinline__ void ldm_x2(uint32& r0, uint32& r1, uint32 addr) {
    asm volatile("ldmatrix.sync.aligned.m8n8.x2.shared.b16 {%0,%1}, [%2];"
                 : "=r"(r0), "=r"(r1) : "r"(addr));
}
__device__ __forceinline__ void mma16816(float* d, const uint32* a, const uint32* b) {
    asm volatile("mma.sync.aligned.m16n8k16.row.col.f32.f16.f16.f32 "
                 "{%0,%1,%2,%3}, {%4,%5,%6,%7}, {%8,%9}, {%10,%11,%12,%13};"
                 : "=f"(d[0]), "=f"(d[1]), "=f"(d[2]), "=f"(d[3])
                 : "r"(a[0]), "r"(a[1]), "r"(a[2]), "r"(a[3]),
                   "r"(b[0]), "r"(b[1]),
                   "f"(d[0]), "f"(d[1]), "f"(d[2]), "f"(d[3]));
}

// -------- node projections + in-smem Wa1 folds + edge packing + global init ---
// Folds recomputed per block (cheap); block 0 publishes g_c0 and zeroes stats.
#define NU 4
__global__ __launch_bounds__(256) void k_node(const float* x, const float* pos,
                                              const float* Wval, const float* Wp,
                                              const float* Wa1, const float* Wsrc,
                                              const float* Wdst, const float* bp,
                                              const float* ba1,
                                              const void* eiv, int E, int n) {
    __shared__ float sd[C * 33], ss[C * 33], sv[C * 33];
    __shared__ float sWp2[C * 3];
    __shared__ int s_is64;
    // ---- is64 detect (int32 read as int64 -> astronomically out of range) ----
    {
        const long long* e64 = (const long long*)eiv;
        int cnt = E < 256 ? E : 256;
        int ok = 1;
        if (threadIdx.x < cnt) {
            long long v = e64[threadIdx.x];
            if (v < 0 || v >= (long long)n) ok = 0;
        }
        int all = __syncthreads_and(ok);
        if (threadIdx.x == 0) s_is64 = all;
    }
    // ---- folds: sd = Wa1@Wdst, ss = Wa1@Wsrc (same FMA order as before) ----
    for (int t = threadIdx.x; t < C * C; t += blockDim.x) {
        int c = t >> 5, m = t & 31;
        float fd = 0.f, fs = 0.f;
        #pragma unroll
        for (int k = 0; k < C; k++) {
            float a = Wa1[c * C + k];
            fd = fmaf(a, Wdst[k * C + m], fd);
            fs = fmaf(a, Wsrc[k * C + m], fs);
        }
        sd[c * 33 + m] = fd;
        ss[c * 33 + m] = fs;
        sv[c * 33 + m] = Wval[t];
    }
    if (threadIdx.x < C * 3) {
        int t = threadIdx.x;
        int c = t / 3, j = t % 3;
        float s_ = 0.f;
        #pragma unroll
        for (int k = 0; k < C; k++) s_ = fmaf(Wa1[c * C + k], Wp[k * 3 + j], s_);
        sWp2[t] = s_;
    }
    if (threadIdx.x < C) {
        int t = threadIdx.x;
        float s_ = 0.f;
        #pragma unroll
        for (int k = 0; k < C; k++) s_ = fmaf(Wa1[t * C + k], bp[k], s_);
        float c0v = s_ + ba1[t];
        if (blockIdx.x == 0) {
            g_c0[t]    = c0v;
            g_sum[t]   = 0.0;
            g_sumsq[t] = 0.0;
        }
    }
    __syncthreads();
    const int lane = threadIdx.x & 31;
    const int warp = (blockIdx.x * blockDim.x + threadIdx.x) >> 5;
    const int nw   = (gridDim.x * blockDim.x) >> 5;
    const float w20 = sWp2[lane * 3 + 0];
    const float w21 = sWp2[lane * 3 + 1];
    const float w22 = sWp2[lane * 3 + 2];
    const float wp0 = Wp[lane * 3 + 0];
    const float wp1 = Wp[lane * 3 + 1];
    const float wp2 = Wp[lane * 3 + 2];
    for (int nd0 = warp * NU; nd0 < n; nd0 += nw * NU) {
        float xv[NU], ad[NU], as_[NU], av[NU];
        #pragma unroll
        for (int u = 0; u < NU; u++) {
            xv[u] = (nd0 + u < n) ? x[(nd0 + u) * C + lane] : 0.f;
            ad[u] = 0.f; as_[u] = 0.f; av[u] = 0.f;
        }
        #pragma unroll
        for (int k = 0; k < C; k++) {
            float wd = sd[lane * 33 + k];
            float ws = ss[lane * 33 + k];
            float wv = sv[lane * 33 + k];
            #pragma unroll
            for (int u = 0; u < NU; u++) {
                float xk = __shfl_sync(FULLMASK, xv[u], k);
                ad[u]  = fmaf(wd, xk, ad[u]);
                as_[u] = fmaf(ws, xk, as_[u]);
                av[u]  = fmaf(wv, xk, av[u]);
            }
        }
        #pragma unroll
        for (int u = 0; u < NU; u++) {
            int nd = nd0 + u;
            if (nd < n) {
                float p0 = pos[nd * 3 + 0];
                float p1 = pos[nd * 3 + 1];
                float p2 = pos[nd * 3 + 2];
                float P  = fmaf(wp0, p0, fmaf(wp1, p1, wp2 * p2));
                float P2 = fmaf(w20, p0, fmaf(w21, p1, w22 * p2));
                ((__half*)g_Hd16)[nd * C + lane] = __float2half_rn(ad[u] + P2);
                ((__half*)g_Hs16)[nd * C + lane] = __float2half_rn(as_[u] + P2);
                g_Vs[nd * C + lane] = av[u] - P;
                g_da2[nd * C + lane] = make_float2(0.f, 0.f);
            }
        }
    }
    // ---- edge packing (moved here from k_preps) ----
    {
        const int is64 = s_is64;
        const long long* e64 = (const long long*)eiv;
        const int*       e32 = (const int*)eiv;
        int i = blockIdx.x * blockDim.x + threadIdx.x;
        int stride = gridDim.x * blockDim.x;
        for (; i < E; i += stride) {
            int s_, d_;
            if (is64) { s_ = (int)e64[i]; d_ = (int)e64[E + i]; }
            else      { s_ = e32[i];      d_ = e32[E + i]; }
            g_edge[i] = make_int2(s_ * C, d_ * C);
        }
    }
}

// ---------- prep+stats, quad-lane gather on fp16 rows; reads packed g_edge ----
__global__ __launch_bounds__(256) void k_preps(int E) {
    __shared__ float sSum[C], sSq[C];
    if (threadIdx.x < C) { sSum[threadIdx.x] = 0.f; sSq[threadIdx.x] = 0.f; }
    __syncthreads();
    const int lane = threadIdx.x & 31;
    const int q    = lane & 7;
    const int el   = lane >> 3;
    const int warp = (blockIdx.x * blockDim.x + threadIdx.x) >> 5;
    const int nw   = (gridDim.x * blockDim.x) >> 5;
    const float4 c04 = *(const float4*)&g_c0[q * 4];
    float s[4]  = {0.f, 0.f, 0.f, 0.f};
    float sq[4] = {0.f, 0.f, 0.f, 0.f};
    for (int base = warp * 32; base < E; base += nw * 32) {
        int cnt = E - base; if (cnt > 32) cnt = 32;
        #pragma unroll
        for (int half = 0; half < 2; half++) {
            int b0 = base + half * 16;
            int hcnt = cnt - half * 16; if (hcnt > 16) hcnt = 16;
            if (hcnt <= 0) break;                       // warp-uniform
            uint2 hd[4], hs[4];
            int ge[4];
            #pragma unroll
            for (int i = 0; i < 4; i++) {
                int e = i * 4 + el;
                ge[i] = b0 + e;
                bool v = e < hcnt;
                int2 eo = v ? g_edge[ge[i]] : make_int2(0, 0);  // 8-way bcast
                hd[i] = v ? g_Hd16[(eo.y >> 2) + q] : make_uint2(0u, 0u);
                hs[i] = v ? g_Hs16[(eo.x >> 2) + q] : make_uint2(0u, 0u);
            }
            #pragma unroll
            for (int i = 0; i < 4; i++) {
                int e = i * 4 + el;
                if (e < hcnt) {
                    float2 d01 = __half22float2(*(__half2*)&hd[i].x);
                    float2 d23 = __half22float2(*(__half2*)&hd[i].y);
                    float2 s01 = __half22float2(*(__half2*)&hs[i].x);
                    float2 s23 = __half22float2(*(__half2*)&hs[i].y);
                    float h0 = d01.x - s01.x + c04.x;
                    float h1 = d01.y - s01.y + c04.y;
                    float h2 = d23.x - s23.x + c04.z;
                    float h3 = d23.y - s23.y + c04.w;
                    s[0] += h0; sq[0] = fmaf(h0, h0, sq[0]);
                    s[1] += h1; sq[1] = fmaf(h1, h1, sq[1]);
                    s[2] += h2; sq[2] = fmaf(h2, h2, sq[2]);
                    s[3] += h3; sq[3] = fmaf(h3, h3, sq[3]);
                    __half2 a01 = __floats2half2_rn(h0, h1);
                    __half2 a23 = __floats2half2_rn(h2, h3);
                    uint2 pk;
                    pk.x = *(uint32*)&a01;
                    pk.y = *(uint32*)&a23;
                    __stcs((uint2*)&g_hh[(long long)ge[i] * C + q * 4], pk);
                }
            }
        }
    }
    #pragma unroll
    for (int j = 0; j < 4; j++) {
        s[j]  += __shfl_down_sync(FULLMASK, s[j], 16);
        s[j]  += __shfl_down_sync(FULLMASK, s[j], 8);
        sq[j] += __shfl_down_sync(FULLMASK, sq[j], 16);
        sq[j] += __shfl_down_sync(FULLMASK, sq[j], 8);
    }
    if (lane < 8) {
        #pragma unroll
        for (int j = 0; j < 4; j++) {
            atomicAdd(&sSum[q * 4 + j], s[j]);
            atomicAdd(&sSq [q * 4 + j], sq[j]);
        }
    }
    __syncthreads();
    if (threadIdx.x < C) {
        atomicAdd(&g_sum  [threadIdx.x], (double)sSum[threadIdx.x]);
        atomicAdd(&g_sumsq[threadIdx.x], (double)sSq [threadIdx.x]);
    }
}

// ------- fused edge pass (frozen R15): fp16 h -> BN/ReLU -> mma.sync GEMM
//         -> smem transpose -> exp -> fused float2 RED scatter
#define HSTR 40   // sH row stride in halves (80B = 16B x 5: ldmatrix-legal)
#define LSTR 34   // sLG row stride in floats (136B: 8B-aligned, coalesced read)
__global__ __launch_bounds__(256) void k_edge(const float* Wa2, const float* ba2,
                                              const float* gamma, const float* beta,
                                              int E) {
    __shared__ __half sWa[C][HSTR];                 // Wa2 fp16 [channel][k]
    __shared__ __align__(16) __half sH[WPB][16][HSTR];
    __shared__ __align__(16) float  sLG[WPB][16][LSTR];
    __shared__ float sgain[C], sb2[C];
    if (threadIdx.x < C) {
        int c = threadIdx.x;
        double mu  = g_sum[c]   / (double)E;
        double var = g_sumsq[c] / (double)E - mu * mu;
        float g = gamma[c] * rsqrtf((float)var + 1e-5f);
        sgain[c] = g;
        sb2[c]   = beta[c] - (float)mu * g;
    }
    for (int t = threadIdx.x; t < C * C; t += blockDim.x)
        sWa[t >> 5][t & 31] = __float2half_rn(Wa2[t]);
    __syncthreads();
    const int lane = threadIdx.x & 31;
    const int q    = lane & 7;
    const int el   = lane >> 3;
    const int wl   = threadIdx.x >> 5;
    const int warp = (blockIdx.x * blockDim.x + threadIdx.x) >> 5;
    const int nw   = (gridDim.x * blockDim.x) >> 5;
    uint32 bfr[2][4][2];
    {
        int r = lane & 7;
        int half8 = (lane >> 3) & 1;
        #pragma unroll
        for (int kt = 0; kt < 2; kt++)
            #pragma unroll
            for (int nt = 0; nt < 4; nt++) {
                uint32 addr = (uint32)__cvta_generic_to_shared(
                    &sWa[nt * 8 + r][kt * 16 + half8 * 8]);
                ldm_x2(bfr[kt][nt][0], bfr[kt][nt][1], addr);
            }
    }
    const float4 gv4 = *(const float4*)&sgain[q * 4];
    const float4 bv4 = *(const float4*)&sb2[q * 4];
    const float  bav = ba2[lane];
    for (int base = warp * 32; base < E; base += nw * 32) {
        int cnt = E - base; if (cnt > 32) cnt = 32;
        int2 ei = make_int2(0, 0);
        if (lane < cnt) ei = g_edge[base + lane];
        #pragma unroll
        for (int grp = 0; grp < 2; grp++) {
            const int g0 = grp * 16;
            int gcnt = cnt - g0; if (gcnt > 16) gcnt = 16;
            if (gcnt <= 0) break;                      // warp-uniform
            // ---- Phase A: quad-lane fp16 h load -> BN/ReLU -> sH ----
            #pragma unroll
            for (int sub = 0; sub < 4; sub++) {
                int e = sub * 4 + el;
                uint2 pk = make_uint2(0u, 0u);
                if (e < gcnt)
                    pk = __ldcs((const uint2*)&g_hh[(long long)(base + g0 + e) * C + q * 4]);
                float2 f01 = __half22float2(*(__half2*)&pk.x);
                float2 f23 = __half22float2(*(__half2*)&pk.y);
                float hn0 = fmaxf(fmaf(f01.x, gv4.x, bv4.x), 0.f);
                float hn1 = fmaxf(fmaf(f01.y, gv4.y, bv4.y), 0.f);
                float hn2 = fmaxf(fmaf(f23.x, gv4.z, bv4.z), 0.f);
                float hn3 = fmaxf(fmaf(f23.y, gv4.w, bv4.w), 0.f);
                __half2 o01 = __floats2half2_rn(hn0, hn1);
                __half2 o23 = __floats2half2_rn(hn2, hn3);
                uint2 opk;
                opk.x = *(uint32*)&o01;
                opk.y = *(uint32*)&o23;
                *(uint2*)&sH[wl][e][q * 4] = opk;
            }
            __syncwarp();
            // ---- Phase B: ldmatrix A + 8 MMA + transpose D to sLG ----
            {
                uint32 afr[2][4];
                int r = lane & 15;
                int hk = lane >> 4;
                #pragma unroll
                for (int kt = 0; kt < 2; kt++) {
                    uint32 addr = (uint32)__cvta_generic_to_shared(
                        &sH[wl][r][kt * 16 + hk * 8]);
                    ldm_x4(afr[kt][0], afr[kt][1], afr[kt][2], afr[kt][3], addr);
                }
                int rowa = lane >> 2;
                int cola = 2 * (lane & 3);
                #pragma unroll
                for (int nt = 0; nt < 4; nt++) {
                    float d[4] = {0.f, 0.f, 0.f, 0.f};
                    mma16816(d, afr[0], bfr[0][nt]);
                    mma16816(d, afr[1], bfr[1][nt]);
                    *(float2*)&sLG[wl][rowa][nt * 8 + cola]     = make_float2(d[0], d[1]);
                    *(float2*)&sLG[wl][rowa + 8][nt * 8 + cola] = make_float2(d[2], d[3]);
                }
            }
            __syncwarp();
            // ---- Phase C: coalesced epilogue (4-deep MLP) ----
            for (int e0 = 0; e0 < 16; e0 += 4) {
                if (e0 >= gcnt) break;                 // warp-uniform
                float fvs[4], lg[4];
                int dofs[4];
                #pragma unroll
                for (int u = 0; u < 4; u++) {
                    int e = e0 + u;
                    int soff = __shfl_sync(FULLMASK, ei.x, g0 + e);
                    dofs[u]  = __shfl_sync(FULLMASK, ei.y, g0 + e);
                    if (e < gcnt) {
                        fvs[u] = g_Vs[soff + lane];
                        lg[u]  = sLG[wl][e][lane];
                    } else { fvs[u] = 0.f; lg[u] = 0.f; }
                }
                #pragma unroll
                for (int u = 0; u < 4; u++) {
                    if (e0 + u < gcnt) {               // warp-uniform
                        float ex = __expf(lg[u] + bav);    // max-free softmax
                        atomicAdd(&g_da2[dofs[u] + lane],
                                  make_float2(ex, ex * fvs[u]));
                    }
                }
            }
            __syncwarp();
        }
    }
}

// -------- final: pd recomputed from pos; out = [(acc+pd*den)/(den+eps)]@Wu^T+bu+x
#define NO 4
__global__ __launch_bounds__(256) void k_out(const float* x, const float* pos,
                                             const float* Wu, const float* Wp,
                                             const float* bp, const float* bu,
                                             float* out, int n) {
    const int lane = threadIdx.x & 31;
    const int warp = (blockIdx.x * blockDim.x + threadIdx.x) >> 5;
    const int nw   = (gridDim.x * blockDim.x) >> 5;
    float wr[C];
    #pragma unroll
    for (int k = 0; k < C; k++) wr[k] = Wu[lane * C + k];
    const float buv = bu[lane];
    const float wp0 = Wp[lane * 3 + 0];
    const float wp1 = Wp[lane * 3 + 1];
    const float wp2 = Wp[lane * 3 + 2];
    const float bpv = bp[lane];
    for (int nd0 = warp * NO; nd0 < n; nd0 += nw * NO) {
        float a[NO], s[NO];
        #pragma unroll
        for (int u = 0; u < NO; u++) {
            int nd = nd0 + u;
            if (nd < n) {
                float2 da = g_da2[nd * C + lane];
                float p0 = pos[nd * 3 + 0];
                float p1 = pos[nd * 3 + 1];
                float p2 = pos[nd * 3 + 2];
                float P  = fmaf(wp0, p0, fmaf(wp1, p1, wp2 * p2));
                float pd = P + bpv;
                a[u] = (da.y + pd * da.x) / (da.x + 1e-16f);
                s[u] = buv + x[nd * C + lane];
            } else { a[u] = 0.f; s[u] = 0.f; }
        }
        #pragma unroll
        for (int k = 0; k < C; k++) {
            float w = wr[k];
            #pragma unroll
            for (int u = 0; u < NO; u++) {
                float ak = __shfl_sync(FULLMASK, a[u], k);
                s[u] = fmaf(w, ak, s[u]);
            }
        }
        #pragma unroll
        for (int u = 0; u < NO; u++)
            if (nd0 + u < n) out[(nd0 + u) * C + lane] = s[u];
    }
}

// ---------------- launch ----------------
extern "C" void kernel_launch(void* const* d_in, const int* in_sizes, int n_in,
                              void* d_out, int out_size) {
    const float* x     = (const float*)d_in[0];
    const float* pos   = (const float*)d_in[1];
    const void*  ei    = d_in[2];
    const float* Wsrc  = (const float*)d_in[3];
    const float* Wdst  = (const float*)d_in[4];
    const float* Wval  = (const float*)d_in[5];
    const float* Wp    = (const float*)d_in[6];
    const float* bp    = (const float*)d_in[7];
    const float* Wa1   = (const float*)d_in[8];
    const float* ba1   = (const float*)d_in[9];
    const float* gamma = (const float*)d_in[10];
    const float* beta  = (const float*)d_in[11];
    const float* Wa2   = (const float*)d_in[12];
    const float* ba2   = (const float*)d_in[13];
    const float* Wu    = (const float*)d_in[14];
    const float* bu    = (const float*)d_in[15];
    float* out = (float*)d_out;

    int n = in_sizes[0] / C;
    int E = in_sizes[2] / 2;

    dim3 gb(1184), tb(256);

    k_node <<<gb, tb>>>(x, pos, Wval, Wp, Wa1, Wsrc, Wdst, bp, ba1, ei, E, n); // 0
    k_preps<<<gb, tb>>>(E);                                // 1
    k_edge <<<gb, tb>>>(Wa2, ba2, gamma, beta, E);         // 2
    k_out  <<<gb, tb>>>(x, pos, Wu, Wp, bp, bu, out, n);   // 3  <- profiled slot
}

// round 17
// speedup vs baseline: 1.2535x; 1.2535x over previous
#include <cuda_runtime.h>
#include <cuda_fp16.h>

#define C 32
#define NMAX 100000
#define EMAX 1600000
#define FULLMASK 0xffffffffu
#define WPB 8          // warps per block (256 threads)

typedef unsigned int uint32;

// ---------------- device scratch ----------------
__device__ uint2  g_Hd16[NMAX * 8];    // fp16 Hd rows: [node][quad] = 4 halves
__device__ uint2  g_Hs16[NMAX * 8];    // fp16 Hs rows
__device__ float  g_Vs [NMAX * C];
__device__ float2 g_da2[NMAX * C];     // per node/channel: {den, acc}
__device__ int2   g_edge[EMAX];        // packed (src*C, dst*C) element offsets
__device__ __half g_hh[(long long)EMAX * C]; // pre-BN h fp16, row layout [e][c]
__device__ float  g_Wcd[C * C];
__device__ float  g_Wcs[C * C];
__device__ float  g_Wp2[C * 3];
__device__ float  g_c0 [C];
__device__ double g_sum  [C];
__device__ double g_sumsq[C];
__device__ int    g_is64;

// ---------------- mma helpers ----------------
__device__ __forceinline__ void ldm_x4(uint32& r0, uint32& r1, uint32& r2, uint32& r3,
                                       uint32 addr) {
    asm volatile("ldmatrix.sync.aligned.m8n8.x4.shared.b16 {%0,%1,%2,%3}, [%4];"
                 : "=r"(r0), "=r"(r1), "=r"(r2), "=r"(r3) : "r"(addr));
}
__device__ __forceinline__ void ldm_x2(uint32& r0, uint32& r1, uint32 addr) {
    asm volatile("ldmatrix.sync.aligned.m8n8.x2.shared.b16 {%0,%1}, [%2];"
                 : "=r"(r0), "=r"(r1) : "r"(addr));
}
__device__ __forceinline__ void mma16816(float* d, const uint32* a, const uint32* b) {
    asm volatile("mma.sync.aligned.m16n8k16.row.col.f32.f16.f16.f32 "
                 "{%0,%1,%2,%3}, {%4,%5,%6,%7}, {%8,%9}, {%10,%11,%12,%13};"
                 : "=f"(d[0]), "=f"(d[1]), "=f"(d[2]), "=f"(d[3])
                 : "r"(a[0]), "r"(a[1]), "r"(a[2]), "r"(a[3]),
                   "r"(b[0]), "r"(b[1]),
                   "f"(d[0]), "f"(d[1]), "f"(d[2]), "f"(d[3]));
}

// -------- detect int64/int32 + fold Wa1 into upstream params + zero sums ------
__global__ void k_detectfold(const long long* ei, int E, int n,
                             const float* Wsrc, const float* Wdst, const float* Wp,
                             const float* bp, const float* Wa1, const float* ba1) {
    int t = threadIdx.x;
    int cnt = E < 256 ? E : 256;
    int ok = 1;
    if (t < cnt) {
        long long v = ei[t];
        if (v < 0 || v >= (long long)n) ok = 0;
    }
    int all = __syncthreads_and(ok);
    if (t == 0) g_is64 = all;
    if (t < C * C) {
        int c = t >> 5, m = t & 31;
        float sd = 0.f, ss = 0.f;
        #pragma unroll
        for (int k = 0; k < C; k++) {
            float a = Wa1[c * C + k];
            sd = fmaf(a, Wdst[k * C + m], sd);
            ss = fmaf(a, Wsrc[k * C + m], ss);
        }
        g_Wcd[t] = sd;
        g_Wcs[t] = ss;
    }
    if (t < C * 3) {
        int c = t / 3, j = t % 3;
        float s = 0.f;
        #pragma unroll
        for (int k = 0; k < C; k++) s = fmaf(Wa1[c * C + k], Wp[k * 3 + j], s);
        g_Wp2[t] = s;
    }
    if (t < C) {
        float s = 0.f;
        #pragma unroll
        for (int k = 0; k < C; k++) s = fmaf(Wa1[t * C + k], bp[k], s);
        g_c0[t] = s + ba1[t];
        g_sum[t] = 0.0;
        g_sumsq[t] = 0.0;
    }
}

// -------- node projections Hd16, Hs16 (fp16), Vs + zero g_da2 --------
#define NU 4
__global__ __launch_bounds__(256) void k_node(const float* x, const float* pos,
                                              const float* Wval, const float* Wp,
                                              int n) {
    __shared__ float sd[C * 33], ss[C * 33], sv[C * 33];
    for (int t = threadIdx.x; t < C * C; t += blockDim.x) {
        int c = t >> 5, k = t & 31;
        sd[c * 33 + k] = g_Wcd[t];
        ss[c * 33 + k] = g_Wcs[t];
        sv[c * 33 + k] = Wval[t];
    }
    __syncthreads();
    const int lane = threadIdx.x & 31;
    const int warp = (blockIdx.x * blockDim.x + threadIdx.x) >> 5;
    const int nw   = (gridDim.x * blockDim.x) >> 5;
    const float w20 = g_Wp2[lane * 3 + 0];
    const float w21 = g_Wp2[lane * 3 + 1];
    const float w22 = g_Wp2[lane * 3 + 2];
    const float wp0 = Wp[lane * 3 + 0];
    const float wp1 = Wp[lane * 3 + 1];
    const float wp2 = Wp[lane * 3 + 2];
    for (int nd0 = warp * NU; nd0 < n; nd0 += nw * NU) {
        float xv[NU], ad[NU], as_[NU], av[NU];
        #pragma unroll
        for (int u = 0; u < NU; u++) {
            xv[u] = (nd0 + u < n) ? x[(nd0 + u) * C + lane] : 0.f;
            ad[u] = 0.f; as_[u] = 0.f; av[u] = 0.f;
        }
        #pragma unroll
        for (int k = 0; k < C; k++) {
            float wd = sd[lane * 33 + k];
            float ws = ss[lane * 33 + k];
            float wv = sv[lane * 33 + k];
            #pragma unroll
            for (int u = 0; u < NU; u++) {
                float xk = __shfl_sync(FULLMASK, xv[u], k);
                ad[u]  = fmaf(wd, xk, ad[u]);
                as_[u] = fmaf(ws, xk, as_[u]);
                av[u]  = fmaf(wv, xk, av[u]);
            }
        }
        #pragma unroll
        for (int u = 0; u < NU; u++) {
            int nd = nd0 + u;
            if (nd < n) {
                float p0 = pos[nd * 3 + 0];
                float p1 = pos[nd * 3 + 1];
                float p2 = pos[nd * 3 + 2];
                float P  = fmaf(wp0, p0, fmaf(wp1, p1, wp2 * p2));
                float P2 = fmaf(w20, p0, fmaf(w21, p1, w22 * p2));
                ((__half*)g_Hd16)[nd * C + lane] = __float2half_rn(ad[u] + P2);
                ((__half*)g_Hs16)[nd * C + lane] = __float2half_rn(as_[u] + P2);
                g_Vs[nd * C + lane] = av[u] - P;
                g_da2[nd * C + lane] = make_float2(0.f, 0.f);
            }
        }
    }
}

// ---------- prep+stats, quad-lane gather on fp16 rows (64B lines) ----------
__global__ __launch_bounds__(256) void k_preps(const void* eiv, int E) {
    __shared__ float sSum[C], sSq[C];
    if (threadIdx.x < C) { sSum[threadIdx.x] = 0.f; sSq[threadIdx.x] = 0.f; }
    __syncthreads();
    const int lane = threadIdx.x & 31;
    const int q    = lane & 7;
    const int el   = lane >> 3;
    const int warp = (blockIdx.x * blockDim.x + threadIdx.x) >> 5;
    const int nw   = (gridDim.x * blockDim.x) >> 5;
    const int is64 = g_is64;
    const long long* e64 = (const long long*)eiv;
    const int*       e32 = (const int*)eiv;
    const float4 c04 = *(const float4*)&g_c0[q * 4];
    float s[4]  = {0.f, 0.f, 0.f, 0.f};
    float sq[4] = {0.f, 0.f, 0.f, 0.f};
    for (int base = warp * 32; base < E; base += nw * 32) {
        int cnt = E - base; if (cnt > 32) cnt = 32;
        if (lane < cnt) {
            int so, dof;
            if (is64) { so = (int)e64[base + lane]; dof = (int)e64[E + base + lane]; }
            else      { so = e32[base + lane];      dof = e32[E + base + lane]; }
            g_edge[base + lane] = make_int2(so * C, dof * C);
        }
        #pragma unroll
        for (int half = 0; half < 2; half++) {
            int b0 = base + half * 16;
            int hcnt = cnt - half * 16; if (hcnt > 16) hcnt = 16;
            if (hcnt <= 0) break;                       // warp-uniform
            uint2 hd[4], hs[4];
            int ge[4];
            #pragma unroll
            for (int i = 0; i < 4; i++) {
                int e = i * 4 + el;
                ge[i] = b0 + e;
                int so = 0, dof = 0;
                bool v = e < hcnt;
                if (v) {
                    if (is64) { so = (int)e64[ge[i]]; dof = (int)e64[E + ge[i]]; }
                    else      { so = e32[ge[i]];      dof = e32[E + ge[i]]; }
                }
                hd[i] = v ? g_Hd16[dof * 8 + q] : make_uint2(0u, 0u);
                hs[i] = v ? g_Hs16[so  * 8 + q] : make_uint2(0u, 0u);
            }
            #pragma unroll
            for (int i = 0; i < 4; i++) {
                int e = i * 4 + el;
                if (e < hcnt) {
                    float2 d01 = __half22float2(*(__half2*)&hd[i].x);
                    float2 d23 = __half22float2(*(__half2*)&hd[i].y);
                    float2 s01 = __half22float2(*(__half2*)&hs[i].x);
                    float2 s23 = __half22float2(*(__half2*)&hs[i].y);
                    float h0 = d01.x - s01.x + c04.x;
                    float h1 = d01.y - s01.y + c04.y;
                    float h2 = d23.x - s23.x + c04.z;
                    float h3 = d23.y - s23.y + c04.w;
                    s[0] += h0; sq[0] = fmaf(h0, h0, sq[0]);
                    s[1] += h1; sq[1] = fmaf(h1, h1, sq[1]);
                    s[2] += h2; sq[2] = fmaf(h2, h2, sq[2]);
                    s[3] += h3; sq[3] = fmaf(h3, h3, sq[3]);
                    __half2 a01 = __floats2half2_rn(h0, h1);
                    __half2 a23 = __floats2half2_rn(h2, h3);
                    uint2 pk;
                    pk.x = *(uint32*)&a01;
                    pk.y = *(uint32*)&a23;
                    __stcs((uint2*)&g_hh[(long long)ge[i] * C + q * 4], pk);
                }
            }
        }
    }
    #pragma unroll
    for (int j = 0; j < 4; j++) {
        s[j]  += __shfl_down_sync(FULLMASK, s[j], 16);
        s[j]  += __shfl_down_sync(FULLMASK, s[j], 8);
        sq[j] += __shfl_down_sync(FULLMASK, sq[j], 16);
        sq[j] += __shfl_down_sync(FULLMASK, sq[j], 8);
    }
    if (lane < 8) {
        #pragma unroll
        for (int j = 0; j < 4; j++) {
            atomicAdd(&sSum[q * 4 + j], s[j]);
            atomicAdd(&sSq [q * 4 + j], sq[j]);
        }
    }
    __syncthreads();
    if (threadIdx.x < C) {
        atomicAdd(&g_sum  [threadIdx.x], (double)sSum[threadIdx.x]);
        atomicAdd(&g_sumsq[threadIdx.x], (double)sSq [threadIdx.x]);
    }
}

// ------- fused edge pass (frozen): fp16 h -> BN/ReLU -> mma.sync GEMM
//         -> smem transpose -> exp -> fused float2 RED scatter
#define HSTR 40   // sH row stride in halves (80B = 16B x 5: ldmatrix-legal)
#define LSTR 34   // sLG row stride in floats (136B: 8B-aligned, coalesced read)
__global__ __launch_bounds__(256) void k_edge(const float* Wa2, const float* ba2,
                                              const float* gamma, const float* beta,
                                              int E) {
    __shared__ __half sWa[C][HSTR];                 // Wa2 fp16 [channel][k]
    __shared__ __align__(16) __half sH[WPB][16][HSTR];
    __shared__ __align__(16) float  sLG[WPB][16][LSTR];
    __shared__ float sgain[C], sb2[C];
    if (threadIdx.x < C) {
        int c = threadIdx.x;
        double mu  = g_sum[c]   / (double)E;
        double var = g_sumsq[c] / (double)E - mu * mu;
        float g = gamma[c] * rsqrtf((float)var + 1e-5f);
        sgain[c] = g;
        sb2[c]   = beta[c] - (float)mu * g;
    }
    for (int t = threadIdx.x; t < C * C; t += blockDim.x)
        sWa[t >> 5][t & 31] = __float2half_rn(Wa2[t]);
    __syncthreads();
    const int lane = threadIdx.x & 31;
    const int q    = lane & 7;
    const int el   = lane >> 3;
    const int wl   = threadIdx.x >> 5;
    const int warp = (blockIdx.x * blockDim.x + threadIdx.x) >> 5;
    const int nw   = (gridDim.x * blockDim.x) >> 5;
    uint32 bfr[2][4][2];
    {
        int r = lane & 7;
        int half8 = (lane >> 3) & 1;
        #pragma unroll
        for (int kt = 0; kt < 2; kt++)
            #pragma unroll
            for (int nt = 0; nt < 4; nt++) {
                uint32 addr = (uint32)__cvta_generic_to_shared(
                    &sWa[nt * 8 + r][kt * 16 + half8 * 8]);
                ldm_x2(bfr[kt][nt][0], bfr[kt][nt][1], addr);
            }
    }
    const float4 gv4 = *(const float4*)&sgain[q * 4];
    const float4 bv4 = *(const float4*)&sb2[q * 4];
    const float  bav = ba2[lane];
    for (int base = warp * 32; base < E; base += nw * 32) {
        int cnt = E - base; if (cnt > 32) cnt = 32;
        int2 ei = make_int2(0, 0);
        if (lane < cnt) ei = g_edge[base + lane];
        #pragma unroll
        for (int grp = 0; grp < 2; grp++) {
            const int g0 = grp * 16;
            int gcnt = cnt - g0; if (gcnt > 16) gcnt = 16;
            if (gcnt <= 0) break;                      // warp-uniform
            // ---- Phase A: quad-lane fp16 h load -> BN/ReLU -> sH ----
            #pragma unroll
            for (int sub = 0; sub < 4; sub++) {
                int e = sub * 4 + el;
                uint2 pk = make_uint2(0u, 0u);
                if (e < gcnt)
                    pk = __ldcs((const uint2*)&g_hh[(long long)(base + g0 + e) * C + q * 4]);
                float2 f01 = __half22float2(*(__half2*)&pk.x);
                float2 f23 = __half22float2(*(__half2*)&pk.y);
                float hn0 = fmaxf(fmaf(f01.x, gv4.x, bv4.x), 0.f);
                float hn1 = fmaxf(fmaf(f01.y, gv4.y, bv4.y), 0.f);
                float hn2 = fmaxf(fmaf(f23.x, gv4.z, bv4.z), 0.f);
                float hn3 = fmaxf(fmaf(f23.y, gv4.w, bv4.w), 0.f);
                __half2 o01 = __floats2half2_rn(hn0, hn1);
                __half2 o23 = __floats2half2_rn(hn2, hn3);
                uint2 opk;
                opk.x = *(uint32*)&o01;
                opk.y = *(uint32*)&o23;
                *(uint2*)&sH[wl][e][q * 4] = opk;
            }
            __syncwarp();
            // ---- Phase B: ldmatrix A + 8 MMA + transpose D to sLG ----
            {
                uint32 afr[2][4];
                int r = lane & 15;
                int hk = lane >> 4;
                #pragma unroll
                for (int kt = 0; kt < 2; kt++) {
                    uint32 addr = (uint32)__cvta_generic_to_shared(
                        &sH[wl][r][kt * 16 + hk * 8]);
                    ldm_x4(afr[kt][0], afr[kt][1], afr[kt][2], afr[kt][3], addr);
                }
                int rowa = lane >> 2;
                int cola = 2 * (lane & 3);
                #pragma unroll
                for (int nt = 0; nt < 4; nt++) {
                    float d[4] = {0.f, 0.f, 0.f, 0.f};
                    mma16816(d, afr[0], bfr[0][nt]);
                    mma16816(d, afr[1], bfr[1][nt]);
                    *(float2*)&sLG[wl][rowa][nt * 8 + cola]     = make_float2(d[0], d[1]);
                    *(float2*)&sLG[wl][rowa + 8][nt * 8 + cola] = make_float2(d[2], d[3]);
                }
            }
            __syncwarp();
            // ---- Phase C: coalesced epilogue (4-deep MLP) ----
            for (int e0 = 0; e0 < 16; e0 += 4) {
                if (e0 >= gcnt) break;                 // warp-uniform
                float fvs[4], lg[4];
                int dofs[4];
                #pragma unroll
                for (int u = 0; u < 4; u++) {
                    int e = e0 + u;
                    int soff = __shfl_sync(FULLMASK, ei.x, g0 + e);
                    dofs[u]  = __shfl_sync(FULLMASK, ei.y, g0 + e);
                    if (e < gcnt) {
                        fvs[u] = g_Vs[soff + lane];
                        lg[u]  = sLG[wl][e][lane];
                    } else { fvs[u] = 0.f; lg[u] = 0.f; }
                }
                #pragma unroll
                for (int u = 0; u < 4; u++) {
                    if (e0 + u < gcnt) {               // warp-uniform
                        float ex = __expf(lg[u] + bav);    // max-free softmax
                        atomicAdd(&g_da2[dofs[u] + lane],
                                  make_float2(ex, ex * fvs[u]));
                    }
                }
            }
            __syncwarp();
        }
    }
}

// -------- final: Wu in smem (reg diet -> occupancy); pd recomputed from pos ----
#define NO 4
__global__ __launch_bounds__(256) void k_out(const float* x, const float* pos,
                                             const float* Wu, const float* Wp,
                                             const float* bp, const float* bu,
                                             float* out, int n) {
    __shared__ float sWu[C * 33];      // [lane][k] stride 33: conflict-free
    for (int t = threadIdx.x; t < C * C; t += blockDim.x)
        sWu[(t >> 5) * 33 + (t & 31)] = Wu[t];
    __syncthreads();
    const int lane = threadIdx.x & 31;
    const int warp = (blockIdx.x * blockDim.x + threadIdx.x) >> 5;
    const int nw   = (gridDim.x * blockDim.x) >> 5;
    const float buv = bu[lane];
    const float wp0 = Wp[lane * 3 + 0];
    const float wp1 = Wp[lane * 3 + 1];
    const float wp2 = Wp[lane * 3 + 2];
    const float bpv = bp[lane];
    const float* wrow = &sWu[lane * 33];
    for (int nd0 = warp * NO; nd0 < n; nd0 += nw * NO) {
        float a[NO], s[NO];
        #pragma unroll
        for (int u = 0; u < NO; u++) {
            int nd = nd0 + u;
            if (nd < n) {
                float2 da = g_da2[nd * C + lane];
                float p0 = pos[nd * 3 + 0];
                float p1 = pos[nd * 3 + 1];
                float p2 = pos[nd * 3 + 2];
                float P  = fmaf(wp0, p0, fmaf(wp1, p1, wp2 * p2));
                float pd = P + bpv;
                a[u] = (da.y + pd * da.x) / (da.x + 1e-16f);
                s[u] = buv + x[nd * C + lane];
            } else { a[u] = 0.f; s[u] = 0.f; }
        }
        #pragma unroll
        for (int k = 0; k < C; k++) {
            float w = wrow[k];                        // LDS, frees 32 regs
            #pragma unroll
            for (int u = 0; u < NO; u++) {
                float ak = __shfl_sync(FULLMASK, a[u], k);
                s[u] = fmaf(w, ak, s[u]);
            }
        }
        #pragma unroll
        for (int u = 0; u < NO; u++)
            if (nd0 + u < n) out[(nd0 + u) * C + lane] = s[u];
    }
}

// ---------------- launch ----------------
extern "C" void kernel_launch(void* const* d_in, const int* in_sizes, int n_in,
                              void* d_out, int out_size) {
    const float* x     = (const float*)d_in[0];
    const float* pos   = (const float*)d_in[1];
    const void*  ei    = d_in[2];
    const float* Wsrc  = (const float*)d_in[3];
    const float* Wdst  = (const float*)d_in[4];
    const float* Wval  = (const float*)d_in[5];
    const float* Wp    = (const float*)d_in[6];
    const float* bp    = (const float*)d_in[7];
    const float* Wa1   = (const float*)d_in[8];
    const float* ba1   = (const float*)d_in[9];
    const float* gamma = (const float*)d_in[10];
    const float* beta  = (const float*)d_in[11];
    const float* Wa2   = (const float*)d_in[12];
    const float* ba2   = (const float*)d_in[13];
    const float* Wu    = (const float*)d_in[14];
    const float* bu    = (const float*)d_in[15];
    float* out = (float*)d_out;

    int n = in_sizes[0] / C;
    int E = in_sizes[2] / 2;

    dim3 gb(1184), tb(256);

    k_detectfold<<<1, 1024>>>((const long long*)ei, E, n, Wsrc, Wdst, Wp, bp, Wa1, ba1); // 0
    k_node <<<gb, tb>>>(x, pos, Wval, Wp, n);              // 1
    k_preps<<<gb, tb>>>(ei, E);                            // 2
    k_edge <<<gb, tb>>>(Wa2, ba2, gamma, beta, E);         // 3  <- profiled slot
    k_out  <<<gb, tb>>>(x, pos, Wu, Wp, bp, bu, out, n);   // 4
}